// round 1
// baseline (speedup 1.0000x reference)
#include <cuda_runtime.h>

#define NT  256
#define BPB 2
#define BATCH 256
#define F_IN 87

__device__ __forceinline__ float fsig(float x) { return 1.0f / (1.0f + __expf(-x)); }

// z[r] = bias[r] + dot(W[r,:], in) for both batch elements; DIN arbitrary (scalar loads)
template<int ROWS, int DIN>
__device__ __forceinline__ void zrows_scalar(
    const float* __restrict__ W, const float* __restrict__ bias,
    const float* __restrict__ in0, const float* __restrict__ in1,
    float* __restrict__ z0, float* __restrict__ z1, int tid)
{
    for (int r = tid; r < ROWS; r += NT) {
        const float* w = W + r * DIN;
        float a0 = __ldg(bias + r);
        float a1 = a0;
#pragma unroll 8
        for (int k = 0; k < DIN; k++) {
            float wv = __ldg(w + k);
            a0 = fmaf(wv, in0[k], a0);
            a1 = fmaf(wv, in1[k], a1);
        }
        z0[r] = a0; z1[r] = a1;
    }
}

// vectorized float4 weight loads; requires DIN % 4 == 0
template<int ROWS, int DIN>
__device__ __forceinline__ void zrows_vec4(
    const float* __restrict__ W, const float* __restrict__ bias,
    const float* __restrict__ in0, const float* __restrict__ in1,
    float* __restrict__ z0, float* __restrict__ z1, int tid)
{
    for (int r = tid; r < ROWS; r += NT) {
        const float4* w = reinterpret_cast<const float4*>(W + r * DIN);
        float a0 = __ldg(bias + r);
        float a1 = a0;
#pragma unroll 8
        for (int k = 0; k < DIN / 4; k++) {
            float4 wv = __ldg(w + k);
            const float* p0 = in0 + 4 * k;
            const float* p1 = in1 + 4 * k;
            a0 = fmaf(wv.x, p0[0], a0); a0 = fmaf(wv.y, p0[1], a0);
            a0 = fmaf(wv.z, p0[2], a0); a0 = fmaf(wv.w, p0[3], a0);
            a1 = fmaf(wv.x, p1[0], a1); a1 = fmaf(wv.y, p1[1], a1);
            a1 = fmaf(wv.z, p1[2], a1); a1 = fmaf(wv.w, p1[3], a1);
        }
        z0[r] = a0; z1[r] = a1;
    }
}

// Single LSTM step from (h=0,c=0), gate order i,f,g,o; then tanh of output.
// c = sigmoid(i)*tanh(g); h = sigmoid(o)*tanh(c); out = tanh(h)
template<int H>
__device__ __forceinline__ void lstm_combine(
    const float* __restrict__ z0, const float* __restrict__ z1,
    float* __restrict__ h0, float* __restrict__ h1, int tid)
{
    for (int j = tid; j < H; j += NT) {
        {
            float gi = z0[j], gg = z0[2 * H + j], go = z0[3 * H + j];
            float c = fsig(gi) * tanhf(gg);
            h0[j] = tanhf(fsig(go) * tanhf(c));
        }
        {
            float gi = z1[j], gg = z1[2 * H + j], go = z1[3 * H + j];
            float c = fsig(gi) * tanhf(gg);
            h1[j] = tanhf(fsig(go) * tanhf(c));
        }
    }
}

template<int DOUT, int DIN, bool RELU>
__device__ __forceinline__ void fc_layer(
    const float* __restrict__ W, const float* __restrict__ bias,
    const float* __restrict__ in0, const float* __restrict__ in1,
    float* __restrict__ o0, float* __restrict__ o1, int tid)
{
    for (int r = tid; r < DOUT; r += NT) {
        const float4* w = reinterpret_cast<const float4*>(W + r * DIN);
        float a0 = __ldg(bias + r);
        float a1 = a0;
#pragma unroll
        for (int k = 0; k < DIN / 4; k++) {
            float4 wv = __ldg(w + k);
            const float* p0 = in0 + 4 * k;
            const float* p1 = in1 + 4 * k;
            a0 = fmaf(wv.x, p0[0], a0); a0 = fmaf(wv.y, p0[1], a0);
            a0 = fmaf(wv.z, p0[2], a0); a0 = fmaf(wv.w, p0[3], a0);
            a1 = fmaf(wv.x, p1[0], a1); a1 = fmaf(wv.y, p1[1], a1);
            a1 = fmaf(wv.z, p1[2], a1); a1 = fmaf(wv.w, p1[3], a1);
        }
        if (RELU) { a0 = fmaxf(a0, 0.0f); a1 = fmaxf(a1, 0.0f); }
        o0[r] = a0; o1[r] = a1;
    }
}

__global__ void __launch_bounds__(NT)
rnn_fused_kernel(
    const float* __restrict__ x,
    const float* __restrict__ w1i, const float* __restrict__ b1,
    const float* __restrict__ w2i, const float* __restrict__ b2,
    const float* __restrict__ w3i, const float* __restrict__ b3,
    const float* __restrict__ w4i, const float* __restrict__ b4,
    const float* __restrict__ f1w, const float* __restrict__ f1b,
    const float* __restrict__ f2w, const float* __restrict__ f2b,
    const float* __restrict__ f3w, const float* __restrict__ f3b,
    const float* __restrict__ f4w, const float* __restrict__ f4b,
    float* __restrict__ out)
{
    __shared__ float zb[BPB][1024];
    __shared__ float hA[BPB][256];
    __shared__ float hB[BPB][256];
    __shared__ float xb[BPB][88];

    const int tid = threadIdx.x;
    const int b0  = blockIdx.x * BPB;

    // x is [T=1024, B=256, F=87]; we need only x[0] -> x0[b][f] = x[b*87+f]
    for (int i = tid; i < F_IN * BPB; i += NT) {
        int p = i / F_IN, f = i - p * F_IN;
        xb[p][f] = __ldg(x + (b0 + p) * F_IN + f);
    }
    __syncthreads();

    // LSTM layer 1: 87 -> 256
    zrows_scalar<1024, 87>(w1i, b1, xb[0], xb[1], zb[0], zb[1], tid);
    __syncthreads();
    lstm_combine<256>(zb[0], zb[1], hA[0], hA[1], tid);
    __syncthreads();

    // LSTM layer 2: 256 -> 128
    zrows_vec4<512, 256>(w2i, b2, hA[0], hA[1], zb[0], zb[1], tid);
    __syncthreads();
    lstm_combine<128>(zb[0], zb[1], hB[0], hB[1], tid);
    __syncthreads();

    // LSTM layer 3: 128 -> 64
    zrows_vec4<256, 128>(w3i, b3, hB[0], hB[1], zb[0], zb[1], tid);
    __syncthreads();
    lstm_combine<64>(zb[0], zb[1], hA[0], hA[1], tid);
    __syncthreads();

    // LSTM layer 4: 64 -> 32 (only t=0 needed)
    zrows_vec4<128, 64>(w4i, b4, hA[0], hA[1], zb[0], zb[1], tid);
    __syncthreads();
    lstm_combine<32>(zb[0], zb[1], hB[0], hB[1], tid);
    __syncthreads();

    // FC stack: 32 -> 128 -> 64 -> 32 -> 3
    fc_layer<128, 32, true>(f1w, f1b, hB[0], hB[1], hA[0], hA[1], tid);
    __syncthreads();
    fc_layer<64, 128, true>(f2w, f2b, hA[0], hA[1], hB[0], hB[1], tid);
    __syncthreads();
    fc_layer<32, 64, true>(f3w, f3b, hB[0], hB[1], hA[0], hA[1], tid);
    __syncthreads();

    // final: 32 -> 3, no relu, write to global
    for (int r = tid; r < 3; r += NT) {
        float a0 = __ldg(f4b + r);
        float a1 = a0;
#pragma unroll
        for (int k = 0; k < 32; k++) {
            float wv = __ldg(f4w + r * 32 + k);
            a0 = fmaf(wv, hA[0][k], a0);
            a1 = fmaf(wv, hA[1][k], a1);
        }
        out[(b0 + 0) * 3 + r] = a0;
        out[(b0 + 1) * 3 + r] = a1;
    }
}

extern "C" void kernel_launch(void* const* d_in, const int* in_sizes, int n_in,
                              void* d_out, int out_size)
{
    // metadata order:
    // 0:x 1:w1i 2:w1h 3:b1 4:w2i 5:w2h 6:b2 7:w3i 8:w3h 9:b3 10:w4i 11:w4h 12:b4
    // 13:f1w 14:f1b 15:f2w 16:f2b 17:f3w 18:f3b 19:f4w 20:f4b
    const float* x   = (const float*)d_in[0];
    const float* w1i = (const float*)d_in[1];
    const float* b1  = (const float*)d_in[3];
    const float* w2i = (const float*)d_in[4];
    const float* b2  = (const float*)d_in[6];
    const float* w3i = (const float*)d_in[7];
    const float* b3  = (const float*)d_in[9];
    const float* w4i = (const float*)d_in[10];
    const float* b4  = (const float*)d_in[12];
    const float* f1w = (const float*)d_in[13];
    const float* f1b = (const float*)d_in[14];
    const float* f2w = (const float*)d_in[15];
    const float* f2b = (const float*)d_in[16];
    const float* f3w = (const float*)d_in[17];
    const float* f3b = (const float*)d_in[18];
    const float* f4w = (const float*)d_in[19];
    const float* f4b = (const float*)d_in[20];
    float* out = (float*)d_out;

    rnn_fused_kernel<<<BATCH / BPB, NT>>>(
        x, w1i, b1, w2i, b2, w3i, b3, w4i, b4,
        f1w, f1b, f2w, f2b, f3w, f3b, f4w, f4b, out);
}

// round 3
// speedup vs baseline: 1.0994x; 1.0994x over previous
#include <cuda_runtime.h>

#define NT   256
#define BPB  4
#define BATCH 256
#define F_IN 87

// ---------------- transposed-weight scratch (device globals: allowed) -------
__device__ float g_wt1[87  * 1024];   // w1i [1024,87]  -> [87][1024]
__device__ float g_wt2[256 * 512];    // w2i [512,256]  -> [256][512]
__device__ float g_wt3[128 * 256];    // w3i [256,128]  -> [128][256]
__device__ float g_wt4[64  * 128];    // w4i [128,64]   -> [64][128]
__device__ float g_ft1[32  * 128];    // f1w [128,32]   -> [32][128]
__device__ float g_ft2[128 * 64];     // f2w [64,128]   -> [128][64]
__device__ float g_ft3[64  * 32];     // f3w [32,64]    -> [64][32]

// ---------------- tiled transpose of all 7 matrices ------------------------
__global__ void __launch_bounds__(256)
transpose_all_kernel(const float* __restrict__ w1i, const float* __restrict__ w2i,
                     const float* __restrict__ w3i, const float* __restrict__ w4i,
                     const float* __restrict__ f1w, const float* __restrict__ f2w,
                     const float* __restrict__ f3w)
{
    __shared__ float tile[32][33];
    int bid = blockIdx.x;
    const float* src; float* dst; int R, C, tcN, lb;

    if      (bid < 96)  { src = w1i; dst = g_wt1; R = 1024; C = 87;  tcN = 3; lb = bid;       }
    else if (bid < 224) { src = w2i; dst = g_wt2; R = 512;  C = 256; tcN = 8; lb = bid - 96;  }
    else if (bid < 256) { src = w3i; dst = g_wt3; R = 256;  C = 128; tcN = 4; lb = bid - 224; }
    else if (bid < 264) { src = w4i; dst = g_wt4; R = 128;  C = 64;  tcN = 2; lb = bid - 256; }
    else if (bid < 268) { src = f1w; dst = g_ft1; R = 128;  C = 32;  tcN = 1; lb = bid - 264; }
    else if (bid < 276) { src = f2w; dst = g_ft2; R = 64;   C = 128; tcN = 4; lb = bid - 268; }
    else                { src = f3w; dst = g_ft3; R = 32;   C = 64;  tcN = 2; lb = bid - 276; }

    const int tr = lb / tcN, tc = lb % tcN;
    const int tx = threadIdx.x & 31, ty = threadIdx.x >> 5;

#pragma unroll
    for (int yy = 0; yy < 4; yy++) {
        int r = tr * 32 + ty + yy * 8;
        int c = tc * 32 + tx;
        if (r < R && c < C) tile[ty + yy * 8][tx] = src[r * C + c];
    }
    __syncthreads();
#pragma unroll
    for (int yy = 0; yy < 4; yy++) {
        int c = tc * 32 + ty + yy * 8;
        int r = tr * 32 + tx;
        if (r < R && c < C) dst[c * R + r] = tile[tx][ty + yy * 8];
    }
}

// ---------------- forward ---------------------------------------------------
__device__ __forceinline__ float fsig(float x) { return 1.0f / (1.0f + __expf(-x)); }

// z[b][r] = bias[r] + sum_k WT[k][r] * in[b][k]; coalesced WT loads.
template<int ROWS, int DIN, int VEC, bool RELU>
__device__ __forceinline__ void dense_t(
    const float* __restrict__ WT, const float* __restrict__ bias,
    const float* __restrict__ in, int in_stride,
    float* __restrict__ outbuf, int out_stride, int tid)
{
    constexpr int ACTIVE = ROWS / VEC;
    if (tid >= ACTIVE) return;
    const int r0 = tid * VEC;

    float acc[BPB][VEC];
#pragma unroll
    for (int v = 0; v < VEC; v++) {
        float bv = __ldg(bias + r0 + v);
#pragma unroll
        for (int b = 0; b < BPB; b++) acc[b][v] = bv;
    }

#pragma unroll 8
    for (int k = 0; k < DIN; k++) {
        float w[VEC];
        if constexpr (VEC == 4) {
            float4 t = __ldg(reinterpret_cast<const float4*>(WT + (size_t)k * ROWS) + tid);
            w[0] = t.x; w[1] = t.y; w[2] = t.z; w[3] = t.w;
        } else if constexpr (VEC == 2) {
            float2 t = __ldg(reinterpret_cast<const float2*>(WT + (size_t)k * ROWS) + tid);
            w[0] = t.x; w[1] = t.y;
        } else {
            w[0] = __ldg(WT + (size_t)k * ROWS + tid);
        }
#pragma unroll
        for (int b = 0; b < BPB; b++) {
            float xv = in[b * in_stride + k];
#pragma unroll
            for (int v = 0; v < VEC; v++) acc[b][v] = fmaf(w[v], xv, acc[b][v]);
        }
    }

#pragma unroll
    for (int b = 0; b < BPB; b++)
#pragma unroll
        for (int v = 0; v < VEC; v++) {
            float a = acc[b][v];
            if (RELU) a = fmaxf(a, 0.0f);
            outbuf[b * out_stride + r0 + v] = a;
        }
}

// single-step LSTM gate combine from (h0=c0=0), plus outer tanh
template<int H>
__device__ __forceinline__ void lstm_combine(
    const float* __restrict__ zb, float* __restrict__ h, int tid)
{
    for (int idx = tid; idx < H * BPB; idx += NT) {
        int b = idx / H, j = idx - b * H;
        const float* z = zb + b * 1024;
        float c = fsig(z[j]) * tanhf(z[2 * H + j]);
        h[b * 256 + j] = tanhf(fsig(z[3 * H + j]) * tanhf(c));
    }
}

__global__ void __launch_bounds__(NT)
rnn_fwd_kernel(
    const float* __restrict__ x,
    const float* __restrict__ b1, const float* __restrict__ b2,
    const float* __restrict__ b3, const float* __restrict__ b4,
    const float* __restrict__ f1b, const float* __restrict__ f2b,
    const float* __restrict__ f3b,
    const float* __restrict__ f4w, const float* __restrict__ f4b,
    float* __restrict__ out)
{
    __shared__ float zb[BPB * 1024];
    __shared__ float hA[BPB * 256];
    __shared__ float hB[BPB * 256];
    __shared__ float xb[BPB * 88];

    const int tid = threadIdx.x;
    const int b0  = blockIdx.x * BPB;

    // x is [T=1024, B=256, F=87]; need only t=0 slice
    for (int i = tid; i < F_IN * BPB; i += NT) {
        int p = i / F_IN, f = i - p * F_IN;
        xb[p * 88 + f] = __ldg(x + (b0 + p) * F_IN + f);
    }
    __syncthreads();

    // LSTM1: 87 -> 256 (rows 1024)
    dense_t<1024, 87, 4, false>(g_wt1, b1, xb, 88, zb, 1024, tid);
    __syncthreads();
    lstm_combine<256>(zb, hA, tid);
    __syncthreads();

    // LSTM2: 256 -> 128 (rows 512)
    dense_t<512, 256, 2, false>(g_wt2, b2, hA, 256, zb, 1024, tid);
    __syncthreads();
    lstm_combine<128>(zb, hB, tid);
    __syncthreads();

    // LSTM3: 128 -> 64 (rows 256)
    dense_t<256, 128, 1, false>(g_wt3, b3, hB, 256, zb, 1024, tid);
    __syncthreads();
    lstm_combine<64>(zb, hA, tid);
    __syncthreads();

    // LSTM4: 64 -> 32 (rows 128)
    dense_t<128, 64, 1, false>(g_wt4, b4, hA, 256, zb, 1024, tid);
    __syncthreads();
    lstm_combine<32>(zb, hB, tid);
    __syncthreads();

    // FC1: 32 -> 128 relu
    dense_t<128, 32, 1, true>(g_ft1, f1b, hB, 256, hA, 256, tid);
    __syncthreads();
    // FC2: 128 -> 64 relu
    dense_t<64, 128, 1, true>(g_ft2, f2b, hA, 256, hB, 256, tid);
    __syncthreads();
    // FC3: 64 -> 32 relu
    dense_t<32, 64, 1, true>(g_ft3, f3b, hB, 256, hA, 256, tid);
    __syncthreads();

    // FC4: 32 -> 3 (tiny, row-major direct)
    if (tid < 3 * BPB) {
        int b = tid / 3, r = tid - b * 3;
        float a = __ldg(f4b + r);
#pragma unroll
        for (int k = 0; k < 32; k++)
            a = fmaf(__ldg(f4w + r * 32 + k), hA[b * 256 + k], a);
        out[(b0 + b) * 3 + r] = a;
    }
}

extern "C" void kernel_launch(void* const* d_in, const int* in_sizes, int n_in,
                              void* d_out, int out_size)
{
    const float* x   = (const float*)d_in[0];
    const float* w1i = (const float*)d_in[1];
    const float* b1  = (const float*)d_in[3];
    const float* w2i = (const float*)d_in[4];
    const float* b2  = (const float*)d_in[6];
    const float* w3i = (const float*)d_in[7];
    const float* b3  = (const float*)d_in[9];
    const float* w4i = (const float*)d_in[10];
    const float* b4  = (const float*)d_in[12];
    const float* f1w = (const float*)d_in[13];
    const float* f1b = (const float*)d_in[14];
    const float* f2w = (const float*)d_in[15];
    const float* f2b = (const float*)d_in[16];
    const float* f3w = (const float*)d_in[17];
    const float* f3b = (const float*)d_in[18];
    const float* f4w = (const float*)d_in[19];
    const float* f4b = (const float*)d_in[20];
    float* out = (float*)d_out;

    transpose_all_kernel<<<278, 256>>>(w1i, w2i, w3i, w4i, f1w, f2w, f3w);
    rnn_fwd_kernel<<<BATCH / BPB, NT>>>(
        x, b1, b2, b3, b4, f1b, f2b, f3b, f4w, f4b, out);
}

// round 4
// speedup vs baseline: 1.1635x; 1.0583x over previous
#include <cuda_runtime.h>

typedef unsigned long long ull;

#define NT   256
#define BPB  4
#define BATCH 256

// ---------------- transposed-weight scratch (device globals: allowed) -------
// layer1 K padded 87 -> 96 (zeros) so DIN % 8 == 0
__device__ __align__(16) float g_wt1[96  * 1024];
__device__ __align__(16) float g_wt2[256 * 512];
__device__ __align__(16) float g_wt3[128 * 256];
__device__ __align__(16) float g_wt4[64  * 128];
__device__ __align__(16) float g_ft1[32  * 128];
__device__ __align__(16) float g_ft2[128 * 64];
__device__ __align__(16) float g_ft3[64  * 32];

// ---------------- tiled transpose of all 7 matrices ------------------------
__global__ void __launch_bounds__(256)
transpose_all_kernel(const float* __restrict__ w1i, const float* __restrict__ w2i,
                     const float* __restrict__ w3i, const float* __restrict__ w4i,
                     const float* __restrict__ f1w, const float* __restrict__ f2w,
                     const float* __restrict__ f3w)
{
    __shared__ float tile[32][33];
    int bid = blockIdx.x;
    const float* src; float* dst; int R, C, Cpad, tcN, lb;

    if      (bid < 96)  { src = w1i; dst = g_wt1; R = 1024; C = 87;  Cpad = 96;  tcN = 3; lb = bid;       }
    else if (bid < 224) { src = w2i; dst = g_wt2; R = 512;  C = 256; Cpad = 256; tcN = 8; lb = bid - 96;  }
    else if (bid < 256) { src = w3i; dst = g_wt3; R = 256;  C = 128; Cpad = 128; tcN = 4; lb = bid - 224; }
    else if (bid < 264) { src = w4i; dst = g_wt4; R = 128;  C = 64;  Cpad = 64;  tcN = 2; lb = bid - 256; }
    else if (bid < 268) { src = f1w; dst = g_ft1; R = 128;  C = 32;  Cpad = 32;  tcN = 1; lb = bid - 264; }
    else if (bid < 276) { src = f2w; dst = g_ft2; R = 64;   C = 128; Cpad = 128; tcN = 4; lb = bid - 268; }
    else                { src = f3w; dst = g_ft3; R = 32;   C = 64;  Cpad = 64;  tcN = 2; lb = bid - 276; }

    const int tr = lb / tcN, tc = lb % tcN;
    const int tx = threadIdx.x & 31, ty = threadIdx.x >> 5;

#pragma unroll
    for (int yy = 0; yy < 4; yy++) {
        int r = tr * 32 + ty + yy * 8;
        int c = tc * 32 + tx;
        tile[ty + yy * 8][tx] = (r < R && c < C) ? src[r * C + c] : 0.0f;
    }
    __syncthreads();
#pragma unroll
    for (int yy = 0; yy < 4; yy++) {
        int c = tc * 32 + ty + yy * 8;
        int r = tr * 32 + tx;
        if (r < R && c < Cpad) dst[c * R + r] = tile[tx][ty + yy * 8];
    }
}

// ---------------- packed fp32x2 helpers -------------------------------------
__device__ __forceinline__ ull pk2(float lo, float hi) {
    ull r; asm("mov.b64 %0, {%1, %2};" : "=l"(r) : "f"(lo), "f"(hi)); return r;
}
__device__ __forceinline__ void upk(ull v, float& lo, float& hi) {
    asm("mov.b64 {%0, %1}, %2;" : "=f"(lo), "=f"(hi) : "l"(v));
}
__device__ __forceinline__ ull ffma2(ull a, ull b, ull c) {
    ull d; asm("fma.rn.f32x2 %0, %1, %2, %3;" : "=l"(d) : "l"(a), "l"(b), "l"(c)); return d;
}
__device__ __forceinline__ float fsig(float x) { return 1.0f / (1.0f + __expf(-x)); }

// ---------------- pipelined packed dense ------------------------------------
// z[b][r] = bias[r] + sum_k WT[k][r] * x[b][k], rows packed in f32x2 pairs.
// OMODE: 0 -> write float z to zout (stride 1024)
//        2 -> relu + write dup-packed {h,h} to hout (stride 256)
template<int ROWS, int DIN, int VEC, int U, int OMODE>
__device__ __forceinline__ void dense_p(
    const float* __restrict__ WT, const float* __restrict__ bias,
    const ull* __restrict__ xin, int xstride,
    float* __restrict__ zout, ull* __restrict__ hout, int tid)
{
    constexpr int ACTIVE = ROWS / VEC;
    constexpr int NP = VEC / 2;
    static_assert(DIN % U == 0 && DIN > U, "pipeline shape");
    if (tid >= ACTIVE) return;
    const int r0 = tid * VEC;

    ull acc[BPB][NP];
#pragma unroll
    for (int p = 0; p < NP; p++) {
        ull bb = pk2(__ldg(bias + r0 + 2 * p), __ldg(bias + r0 + 2 * p + 1));
#pragma unroll
        for (int b = 0; b < BPB; b++) acc[b][p] = bb;
    }

    if constexpr (VEC == 4) {
        constexpr int KS = ROWS / 4;
        const ulonglong2* base = reinterpret_cast<const ulonglong2*>(WT) + tid;
        ulonglong2 buf[U];
#pragma unroll
        for (int u = 0; u < U; u++) buf[u] = __ldg(base + u * KS);

        for (int k0 = 0; k0 < DIN - U; k0 += U) {
#pragma unroll
            for (int u = 0; u < U; u++) {
                ull wlo = buf[u].x, whi = buf[u].y;
#pragma unroll
                for (int b = 0; b < BPB; b++) {
                    ull xd = xin[b * xstride + k0 + u];
                    acc[b][0] = ffma2(wlo, xd, acc[b][0]);
                    acc[b][1] = ffma2(whi, xd, acc[b][1]);
                }
                buf[u] = __ldg(base + (k0 + U + u) * KS);   // prefetch k0+U+u
            }
        }
#pragma unroll
        for (int u = 0; u < U; u++) {                       // tail, no loads
            ull wlo = buf[u].x, whi = buf[u].y;
#pragma unroll
            for (int b = 0; b < BPB; b++) {
                ull xd = xin[b * xstride + (DIN - U) + u];
                acc[b][0] = ffma2(wlo, xd, acc[b][0]);
                acc[b][1] = ffma2(whi, xd, acc[b][1]);
            }
        }
    } else {  // VEC == 2
        constexpr int KS = ROWS / 2;
        const ull* base = reinterpret_cast<const ull*>(WT) + tid;
        ull buf[U];
#pragma unroll
        for (int u = 0; u < U; u++) buf[u] = __ldg(base + u * KS);

        for (int k0 = 0; k0 < DIN - U; k0 += U) {
#pragma unroll
            for (int u = 0; u < U; u++) {
                ull w = buf[u];
#pragma unroll
                for (int b = 0; b < BPB; b++)
                    acc[b][0] = ffma2(w, xin[b * xstride + k0 + u], acc[b][0]);
                buf[u] = __ldg(base + (k0 + U + u) * KS);
            }
        }
#pragma unroll
        for (int u = 0; u < U; u++) {
            ull w = buf[u];
#pragma unroll
            for (int b = 0; b < BPB; b++)
                acc[b][0] = ffma2(w, xin[b * xstride + (DIN - U) + u], acc[b][0]);
        }
    }

#pragma unroll
    for (int b = 0; b < BPB; b++)
#pragma unroll
        for (int p = 0; p < NP; p++) {
            float lo, hi; upk(acc[b][p], lo, hi);
            if constexpr (OMODE == 0) {
                zout[b * 1024 + r0 + 2 * p]     = lo;
                zout[b * 1024 + r0 + 2 * p + 1] = hi;
            } else {
                lo = fmaxf(lo, 0.0f); hi = fmaxf(hi, 0.0f);
                hout[b * 256 + r0 + 2 * p]     = pk2(lo, lo);
                hout[b * 256 + r0 + 2 * p + 1] = pk2(hi, hi);
            }
        }
}

// single-step LSTM combine from (h0=c0=0) + outer tanh; writes dup-packed h
template<int H>
__device__ __forceinline__ void lstm_combine(
    const float* __restrict__ zb, ull* __restrict__ hd, int tid)
{
    for (int idx = tid; idx < H * BPB; idx += NT) {
        int b = idx / H, j = idx - b * H;
        const float* z = zb + b * 1024;
        float c = fsig(z[j]) * tanhf(z[2 * H + j]);
        float h = tanhf(fsig(z[3 * H + j]) * tanhf(c));
        hd[b * 256 + j] = pk2(h, h);
    }
}

__global__ void __launch_bounds__(NT)
rnn_fwd_kernel(
    const float* __restrict__ x,
    const float* __restrict__ b1, const float* __restrict__ b2,
    const float* __restrict__ b3, const float* __restrict__ b4,
    const float* __restrict__ f1b, const float* __restrict__ f2b,
    const float* __restrict__ f3b,
    const float* __restrict__ f4w, const float* __restrict__ f4b,
    float* __restrict__ out)
{
    __shared__ float zb[BPB * 1024];   // 16 KB
    __shared__ ull   hA[BPB * 256];    //  8 KB
    __shared__ ull   hB[BPB * 256];    //  8 KB
    __shared__ ull   xd[BPB * 96];     //  3 KB

    const int tid = threadIdx.x;
    const int b0  = blockIdx.x * BPB;

    // x is [T=1024, B=256, F=87]; need only t=0; dup-pack, zero-pad K to 96
    for (int i = tid; i < 96 * BPB; i += NT) {
        int p = i / 96, f = i - p * 96;
        float v = (f < 87) ? __ldg(x + (b0 + p) * 87 + f) : 0.0f;
        xd[p * 96 + f] = pk2(v, v);
    }
    __syncthreads();

    // LSTM1: 87(->96) -> 256
    dense_p<1024, 96, 4, 8, 0>(g_wt1, b1, xd, 96, zb, nullptr, tid);
    __syncthreads();
    lstm_combine<256>(zb, hA, tid);
    __syncthreads();

    // LSTM2: 256 -> 128
    dense_p<512, 256, 2, 8, 0>(g_wt2, b2, hA, 256, zb, nullptr, tid);
    __syncthreads();
    lstm_combine<128>(zb, hB, tid);
    __syncthreads();

    // LSTM3: 128 -> 64
    dense_p<256, 128, 2, 8, 0>(g_wt3, b3, hB, 256, zb, nullptr, tid);
    __syncthreads();
    lstm_combine<64>(zb, hA, tid);
    __syncthreads();

    // LSTM4: 64 -> 32
    dense_p<128, 64, 2, 8, 0>(g_wt4, b4, hA, 256, zb, nullptr, tid);
    __syncthreads();
    lstm_combine<32>(zb, hB, tid);
    __syncthreads();

    // FC1: 32 -> 128 relu
    dense_p<128, 32, 2, 8, 2>(g_ft1, f1b, hB, 256, nullptr, hA, tid);
    __syncthreads();
    // FC2: 128 -> 64 relu
    dense_p<64, 128, 2, 8, 2>(g_ft2, f2b, hA, 256, nullptr, hB, tid);
    __syncthreads();
    // FC3: 64 -> 32 relu
    dense_p<32, 64, 2, 8, 2>(g_ft3, f3b, hB, 256, nullptr, hA, tid);
    __syncthreads();

    // FC4: 32 -> 3 (tiny, row-major direct)
    if (tid < 3 * BPB) {
        int b = tid / 3, r = tid - b * 3;
        float a = __ldg(f4b + r);
#pragma unroll
        for (int k = 0; k < 32; k++) {
            float lo, hi; upk(hA[b * 256 + k], lo, hi);
            a = fmaf(__ldg(f4w + r * 32 + k), lo, a);
        }
        out[(b0 + b) * 3 + r] = a;
    }
}

extern "C" void kernel_launch(void* const* d_in, const int* in_sizes, int n_in,
                              void* d_out, int out_size)
{
    const float* x   = (const float*)d_in[0];
    const float* w1i = (const float*)d_in[1];
    const float* b1  = (const float*)d_in[3];
    const float* w2i = (const float*)d_in[4];
    const float* b2  = (const float*)d_in[6];
    const float* w3i = (const float*)d_in[7];
    const float* b3  = (const float*)d_in[9];
    const float* w4i = (const float*)d_in[10];
    const float* b4  = (const float*)d_in[12];
    const float* f1w = (const float*)d_in[13];
    const float* f1b = (const float*)d_in[14];
    const float* f2w = (const float*)d_in[15];
    const float* f2b = (const float*)d_in[16];
    const float* f3w = (const float*)d_in[17];
    const float* f3b = (const float*)d_in[18];
    const float* f4w = (const float*)d_in[19];
    const float* f4b = (const float*)d_in[20];
    float* out = (float*)d_out;

    transpose_all_kernel<<<278, 256>>>(w1i, w2i, w3i, w4i, f1w, f2w, f3w);
    rnn_fwd_kernel<<<BATCH / BPB, NT>>>(
        x, b1, b2, b3, b4, f1b, f2b, f3b, f4w, f4b, out);
}

// round 5
// speedup vs baseline: 2.0035x; 1.7220x over previous
#include <cuda_runtime.h>

typedef unsigned long long ull;

#define NT2  512
#define BPB  4
#define BATCH 256

// ---------------- transposed-weight scratch (device globals: allowed) -------
// layer1 K padded 87 -> 96 (zeros) so slices stay multiple of 8
__device__ __align__(16) float g_wt1[96  * 1024];
__device__ __align__(16) float g_wt2[256 * 512];
__device__ __align__(16) float g_wt3[128 * 256];
__device__ __align__(16) float g_wt4[64  * 128];
__device__ __align__(16) float g_ft1[32  * 128];
__device__ __align__(16) float g_ft2[128 * 64];
__device__ __align__(16) float g_ft3[64  * 32];

// ---------------- tiled transpose of all 7 matrices ------------------------
__global__ void __launch_bounds__(256)
transpose_all_kernel(const float* __restrict__ w1i, const float* __restrict__ w2i,
                     const float* __restrict__ w3i, const float* __restrict__ w4i,
                     const float* __restrict__ f1w, const float* __restrict__ f2w,
                     const float* __restrict__ f3w)
{
    __shared__ float tile[32][33];
    int bid = blockIdx.x;
    const float* src; float* dst; int R, C, Cpad, tcN, lb;

    if      (bid < 96)  { src = w1i; dst = g_wt1; R = 1024; C = 87;  Cpad = 96;  tcN = 3; lb = bid;       }
    else if (bid < 224) { src = w2i; dst = g_wt2; R = 512;  C = 256; Cpad = 256; tcN = 8; lb = bid - 96;  }
    else if (bid < 256) { src = w3i; dst = g_wt3; R = 256;  C = 128; Cpad = 128; tcN = 4; lb = bid - 224; }
    else if (bid < 264) { src = w4i; dst = g_wt4; R = 128;  C = 64;  Cpad = 64;  tcN = 2; lb = bid - 256; }
    else if (bid < 268) { src = f1w; dst = g_ft1; R = 128;  C = 32;  Cpad = 32;  tcN = 1; lb = bid - 264; }
    else if (bid < 276) { src = f2w; dst = g_ft2; R = 64;   C = 128; Cpad = 128; tcN = 4; lb = bid - 268; }
    else                { src = f3w; dst = g_ft3; R = 32;   C = 64;  Cpad = 64;  tcN = 2; lb = bid - 276; }

    const int tr = lb / tcN, tc = lb % tcN;
    const int tx = threadIdx.x & 31, ty = threadIdx.x >> 5;

#pragma unroll
    for (int yy = 0; yy < 4; yy++) {
        int r = tr * 32 + ty + yy * 8;
        int c = tc * 32 + tx;
        tile[ty + yy * 8][tx] = (r < R && c < C) ? src[r * C + c] : 0.0f;
    }
    __syncthreads();
#pragma unroll
    for (int yy = 0; yy < 4; yy++) {
        int c = tc * 32 + ty + yy * 8;
        int r = tr * 32 + tx;
        if (r < R && c < Cpad) dst[c * R + r] = tile[tx][ty + yy * 8];
    }
}

// ---------------- packed fp32x2 helpers -------------------------------------
__device__ __forceinline__ ull pk2(float lo, float hi) {
    ull r; asm("mov.b64 %0, {%1, %2};" : "=l"(r) : "f"(lo), "f"(hi)); return r;
}
__device__ __forceinline__ void upk(ull v, float& lo, float& hi) {
    asm("mov.b64 {%0, %1}, %2;" : "=f"(lo), "=f"(hi) : "l"(v));
}
__device__ __forceinline__ ull ffma2(ull a, ull b, ull c) {
    ull d; asm("fma.rn.f32x2 %0, %1, %2, %3;" : "=l"(d) : "l"(a), "l"(b), "l"(c)); return d;
}
__device__ __forceinline__ float fsig(float x) { return 1.0f / (1.0f + __expf(-x)); }

// ---------------- K-split dense: z partials into zb (slice0) / pb -----------
// WT is [DIN][ROWS]. Thread layout: slice s = tid/ACTIVE handles k in
// [s*KS, (s+1)*KS); lane r = tid%ACTIVE handles VEC consecutive rows.
// slice 0 adds bias and writes zb[b*ROWS + row]; slice s>0 writes
// pb[(s-1)*ROWS*BPB + b*ROWS + row]. Raw z only; activation in combine.
template<int ROWS, int DIN, int VEC, int S>
__device__ __forceinline__ void dense_ks(
    const float* __restrict__ WT, const float* __restrict__ bias,
    const ull* __restrict__ xin, int xstride,          // dup-packed {v,v}
    float* __restrict__ zb, float* __restrict__ pb, int tid)
{
    constexpr int ACTIVE = ROWS / VEC;
    constexpr int KS = DIN / S;
    static_assert(ACTIVE * S <= NT2, "thread layout");
    static_assert(KS % 8 == 0 || KS < 32, "slice shape");
    if (tid >= ACTIVE * S) return;
    const int s  = tid / ACTIVE;
    const int r  = tid - s * ACTIVE;
    const int kb = s * KS;
    float* outp = (s == 0) ? zb : (pb + (s - 1) * (ROWS * BPB));
    const float* xf = reinterpret_cast<const float*>(xin);

    if constexpr (VEC == 4) {
        constexpr int W4 = ROWS / 4;
        const int r0 = r * 4;
        const ulonglong2* base = reinterpret_cast<const ulonglong2*>(WT) + r;
        ull acc[BPB][2];
#pragma unroll
        for (int b = 0; b < BPB; b++) {
            acc[b][0] = (s == 0) ? pk2(__ldg(bias + r0),     __ldg(bias + r0 + 1)) : 0ull;
            acc[b][1] = (s == 0) ? pk2(__ldg(bias + r0 + 2), __ldg(bias + r0 + 3)) : 0ull;
        }
        ulonglong2 buf[8];
#pragma unroll
        for (int u = 0; u < 8; u++) buf[u] = __ldg(base + (kb + u) * W4);
        for (int k0 = 0; k0 < KS - 8; k0 += 8) {
#pragma unroll
            for (int u = 0; u < 8; u++) {
                ull wlo = buf[u].x, whi = buf[u].y;
#pragma unroll
                for (int b = 0; b < BPB; b++) {
                    ull xd2 = xin[b * xstride + kb + k0 + u];
                    acc[b][0] = ffma2(wlo, xd2, acc[b][0]);
                    acc[b][1] = ffma2(whi, xd2, acc[b][1]);
                }
                buf[u] = __ldg(base + (kb + k0 + 8 + u) * W4);
            }
        }
#pragma unroll
        for (int u = 0; u < 8; u++) {
            ull wlo = buf[u].x, whi = buf[u].y;
#pragma unroll
            for (int b = 0; b < BPB; b++) {
                ull xd2 = xin[b * xstride + kb + (KS - 8) + u];
                acc[b][0] = ffma2(wlo, xd2, acc[b][0]);
                acc[b][1] = ffma2(whi, xd2, acc[b][1]);
            }
        }
#pragma unroll
        for (int b = 0; b < BPB; b++) {
            float l0, h0, l1, h1;
            upk(acc[b][0], l0, h0); upk(acc[b][1], l1, h1);
            outp[b * ROWS + r0]     = l0;
            outp[b * ROWS + r0 + 1] = h0;
            outp[b * ROWS + r0 + 2] = l1;
            outp[b * ROWS + r0 + 3] = h1;
        }
    } else if constexpr (VEC == 2) {
        constexpr int W2 = ROWS / 2;
        const int r0 = r * 2;
        const ull* base = reinterpret_cast<const ull*>(WT) + r;
        ull acc[BPB];
#pragma unroll
        for (int b = 0; b < BPB; b++)
            acc[b] = (s == 0) ? pk2(__ldg(bias + r0), __ldg(bias + r0 + 1)) : 0ull;
        ull buf[8];
#pragma unroll
        for (int u = 0; u < 8; u++) buf[u] = __ldg(base + (kb + u) * W2);
        for (int k0 = 0; k0 < KS - 8; k0 += 8) {
#pragma unroll
            for (int u = 0; u < 8; u++) {
                ull w = buf[u];
#pragma unroll
                for (int b = 0; b < BPB; b++)
                    acc[b] = ffma2(w, xin[b * xstride + kb + k0 + u], acc[b]);
                buf[u] = __ldg(base + (kb + k0 + 8 + u) * W2);
            }
        }
#pragma unroll
        for (int u = 0; u < 8; u++) {
            ull w = buf[u];
#pragma unroll
            for (int b = 0; b < BPB; b++)
                acc[b] = ffma2(w, xin[b * xstride + kb + (KS - 8) + u], acc[b]);
        }
#pragma unroll
        for (int b = 0; b < BPB; b++) {
            float lo, hi; upk(acc[b], lo, hi);
            outp[b * ROWS + r0]     = lo;
            outp[b * ROWS + r0 + 1] = hi;
        }
    } else {  // VEC == 1, scalar rows
        float acc[BPB];
        float bv = (s == 0) ? __ldg(bias + r) : 0.0f;
#pragma unroll
        for (int b = 0; b < BPB; b++) acc[b] = bv;
        if constexpr (KS >= 32) {
            float buf[8];
#pragma unroll
            for (int u = 0; u < 8; u++) buf[u] = __ldg(WT + (kb + u) * ROWS + r);
            for (int k0 = 0; k0 < KS - 8; k0 += 8) {
#pragma unroll
                for (int u = 0; u < 8; u++) {
                    float w = buf[u];
#pragma unroll
                    for (int b = 0; b < BPB; b++)
                        acc[b] = fmaf(w, xf[2 * (b * xstride + kb + k0 + u)], acc[b]);
                    buf[u] = __ldg(WT + (kb + k0 + 8 + u) * ROWS + r);
                }
            }
#pragma unroll
            for (int u = 0; u < 8; u++) {
                float w = buf[u];
#pragma unroll
                for (int b = 0; b < BPB; b++)
                    acc[b] = fmaf(w, xf[2 * (b * xstride + kb + (KS - 8) + u)], acc[b]);
            }
        } else {
#pragma unroll
            for (int k = 0; k < KS; k++) {
                float w = __ldg(WT + (kb + k) * ROWS + r);
#pragma unroll
                for (int b = 0; b < BPB; b++)
                    acc[b] = fmaf(w, xf[2 * (b * xstride + kb + k)], acc[b]);
            }
        }
#pragma unroll
        for (int b = 0; b < BPB; b++) outp[b * ROWS + r] = acc[b];
    }
}

// sum S partials, LSTM single-step combine (h0=c0=0) + outer tanh, dup-pack
template<int H, int S>
__device__ __forceinline__ void lstm_combine(
    const float* __restrict__ zb, const float* __restrict__ pb,
    ull* __restrict__ hd, int tid)
{
    constexpr int ROWS = 4 * H;
    for (int idx = tid; idx < H * BPB; idx += NT2) {
        int b = idx / H, j = idx - b * H;
        float zi = zb[b * ROWS + j];
        float zg = zb[b * ROWS + 2 * H + j];
        float zo = zb[b * ROWS + 3 * H + j];
#pragma unroll
        for (int s = 1; s < S; s++) {
            const float* p = pb + (s - 1) * (ROWS * BPB) + b * ROWS;
            zi += p[j]; zg += p[2 * H + j]; zo += p[3 * H + j];
        }
        float c = fsig(zi) * tanhf(zg);
        float h = tanhf(fsig(zo) * tanhf(c));
        hd[b * 256 + j] = pk2(h, h);
    }
}

// sum S partials + relu, dup-pack into hd (stride 256)
template<int ROWS, int S>
__device__ __forceinline__ void relu_combine(
    const float* __restrict__ zb, const float* __restrict__ pb,
    ull* __restrict__ hd, int tid)
{
    for (int idx = tid; idx < ROWS * BPB; idx += NT2) {
        int b = idx / ROWS, j = idx - b * ROWS;
        float v = zb[b * ROWS + j];
#pragma unroll
        for (int s = 1; s < S; s++)
            v += pb[(s - 1) * (ROWS * BPB) + b * ROWS + j];
        v = fmaxf(v, 0.0f);
        hd[b * 256 + j] = pk2(v, v);
    }
}

__global__ void __launch_bounds__(NT2, 1)
rnn_fwd_kernel(
    const float* __restrict__ x,
    const float* __restrict__ b1, const float* __restrict__ b2,
    const float* __restrict__ b3, const float* __restrict__ b4,
    const float* __restrict__ f1b, const float* __restrict__ f2b,
    const float* __restrict__ f3b,
    const float* __restrict__ f4w, const float* __restrict__ f4b,
    float* __restrict__ out)
{
    __shared__ float zb[BPB * 1024];   // 16 KB  slice-0 partials
    __shared__ float pb[BPB * 1024];   // 16 KB  slice 1..S-1 partials
    __shared__ ull   hA[BPB * 256];    //  8 KB  dup-packed activations
    __shared__ ull   hB[BPB * 256];    //  8 KB  (xd overlaid: dead ranges disjoint)

    ull* xd = hB;                      // x staging lives in hB until L1 dense done

    const int tid = threadIdx.x;
    const int b0  = blockIdx.x * BPB;

    // x is [T=1024, B=256, F=87]; need only t=0; dup-pack, zero-pad K to 96
    for (int i = tid; i < 96 * BPB; i += NT2) {
        int p = i / 96, f = i - p * 96;
        float v = (f < 87) ? __ldg(x + (b0 + p) * 87 + f) : 0.0f;
        xd[p * 96 + f] = pk2(v, v);
    }
    __syncthreads();

    // LSTM1: 87(->96) -> 256   rows=1024, VEC4, S=2 -> 512 threads, 48 k each
    dense_ks<1024, 96, 4, 2>(g_wt1, b1, xd, 96, zb, pb, tid);
    __syncthreads();
    lstm_combine<256, 2>(zb, pb, hA, tid);
    __syncthreads();

    // LSTM2: 256 -> 128        rows=512, VEC2, S=2 -> 512 threads, 128 k each
    dense_ks<512, 256, 2, 2>(g_wt2, b2, hA, 256, zb, pb, tid);
    __syncthreads();
    lstm_combine<128, 2>(zb, pb, hB, tid);
    __syncthreads();

    // LSTM3: 128 -> 64         rows=256, VEC1, S=2 -> 512 threads, 64 k each
    dense_ks<256, 128, 1, 2>(g_wt3, b3, hB, 256, zb, pb, tid);
    __syncthreads();
    lstm_combine<64, 2>(zb, pb, hA, tid);
    __syncthreads();

    // LSTM4: 64 -> 32          rows=128, VEC1, S=4 -> 512 threads, 16 k each
    dense_ks<128, 64, 1, 4>(g_wt4, b4, hA, 256, zb, pb, tid);
    __syncthreads();
    lstm_combine<32, 4>(zb, pb, hB, tid);
    __syncthreads();

    // FC1: 32 -> 128 relu      rows=128, VEC1, S=4 -> 512 threads, 8 k each
    dense_ks<128, 32, 1, 4>(g_ft1, f1b, hB, 256, zb, pb, tid);
    __syncthreads();
    relu_combine<128, 4>(zb, pb, hA, tid);
    __syncthreads();

    // FC2: 128 -> 64 relu      rows=64, VEC1, S=8 -> 512 threads, 16 k each
    dense_ks<64, 128, 1, 8>(g_ft2, f2b, hA, 256, zb, pb, tid);
    __syncthreads();
    relu_combine<64, 8>(zb, pb, hB, tid);
    __syncthreads();

    // FC3: 64 -> 32 relu       rows=32, VEC1, S=8 -> 256 threads, 8 k each
    dense_ks<32, 64, 1, 8>(g_ft3, f3b, hB, 256, zb, pb, tid);
    __syncthreads();
    relu_combine<32, 8>(zb, pb, hA, tid);
    __syncthreads();

    // FC4: 32 -> 3 (tiny, row-major direct)
    if (tid < 3 * BPB) {
        int b = tid / 3, r = tid - b * 3;
        float a = __ldg(f4b + r);
#pragma unroll
        for (int k = 0; k < 32; k++) {
            float lo, hi; upk(hA[b * 256 + k], lo, hi);
            a = fmaf(__ldg(f4w + r * 32 + k), lo, a);
        }
        out[(b0 + b) * 3 + r] = a;
    }
}

extern "C" void kernel_launch(void* const* d_in, const int* in_sizes, int n_in,
                              void* d_out, int out_size)
{
    const float* x   = (const float*)d_in[0];
    const float* w1i = (const float*)d_in[1];
    const float* b1  = (const float*)d_in[3];
    const float* w2i = (const float*)d_in[4];
    const float* b2  = (const float*)d_in[6];
    const float* w3i = (const float*)d_in[7];
    const float* b3  = (const float*)d_in[9];
    const float* w4i = (const float*)d_in[10];
    const float* b4  = (const float*)d_in[12];
    const float* f1w = (const float*)d_in[13];
    const float* f1b = (const float*)d_in[14];
    const float* f2w = (const float*)d_in[15];
    const float* f2b = (const float*)d_in[16];
    const float* f3w = (const float*)d_in[17];
    const float* f3b = (const float*)d_in[18];
    const float* f4w = (const float*)d_in[19];
    const float* f4b = (const float*)d_in[20];
    float* out = (float*)d_out;

    transpose_all_kernel<<<278, 256>>>(w1i, w2i, w3i, w4i, f1w, f2w, f3w);
    rnn_fwd_kernel<<<BATCH / BPB, NT2>>>(
        x, b1, b2, b3, b4, f1b, f2b, f3b, f4w, f4b, out);
}

// round 6
// speedup vs baseline: 2.5867x; 1.2911x over previous
#include <cuda_runtime.h>

typedef unsigned long long ull;

#define NT2  512
#define BPB  2
#define BATCH 256

// ---------------- transposed-weight scratch (device globals: allowed) -------
// layer1 K padded 87 -> 96 (zeros) so slices stay multiple of 8
__device__ __align__(16) float g_wt1[96  * 1024];
__device__ __align__(16) float g_wt2[256 * 512];
__device__ __align__(16) float g_wt3[128 * 256];
__device__ __align__(16) float g_wt4[64  * 128];
__device__ __align__(16) float g_ft1[32  * 128];
__device__ __align__(16) float g_ft2[128 * 64];
__device__ __align__(16) float g_ft3[64  * 32];

// ---------------- tiled transpose of all 7 matrices ------------------------
__global__ void __launch_bounds__(256)
transpose_all_kernel(const float* __restrict__ w1i, const float* __restrict__ w2i,
                     const float* __restrict__ w3i, const float* __restrict__ w4i,
                     const float* __restrict__ f1w, const float* __restrict__ f2w,
                     const float* __restrict__ f3w)
{
    __shared__ float tile[32][33];
    int bid = blockIdx.x;
    const float* src; float* dst; int R, C, Cpad, tcN, lb;

    if      (bid < 96)  { src = w1i; dst = g_wt1; R = 1024; C = 87;  Cpad = 96;  tcN = 3; lb = bid;       }
    else if (bid < 224) { src = w2i; dst = g_wt2; R = 512;  C = 256; Cpad = 256; tcN = 8; lb = bid - 96;  }
    else if (bid < 256) { src = w3i; dst = g_wt3; R = 256;  C = 128; Cpad = 128; tcN = 4; lb = bid - 224; }
    else if (bid < 264) { src = w4i; dst = g_wt4; R = 128;  C = 64;  Cpad = 64;  tcN = 2; lb = bid - 256; }
    else if (bid < 268) { src = f1w; dst = g_ft1; R = 128;  C = 32;  Cpad = 32;  tcN = 1; lb = bid - 264; }
    else if (bid < 276) { src = f2w; dst = g_ft2; R = 64;   C = 128; Cpad = 128; tcN = 4; lb = bid - 268; }
    else                { src = f3w; dst = g_ft3; R = 32;   C = 64;  Cpad = 64;  tcN = 2; lb = bid - 276; }

    const int tr = lb / tcN, tc = lb % tcN;
    const int tx = threadIdx.x & 31, ty = threadIdx.x >> 5;

#pragma unroll
    for (int yy = 0; yy < 4; yy++) {
        int r = tr * 32 + ty + yy * 8;
        int c = tc * 32 + tx;
        tile[ty + yy * 8][tx] = (r < R && c < C) ? src[r * C + c] : 0.0f;
    }
    __syncthreads();
#pragma unroll
    for (int yy = 0; yy < 4; yy++) {
        int c = tc * 32 + ty + yy * 8;
        int r = tr * 32 + tx;
        if (r < R && c < Cpad) dst[c * R + r] = tile[tx][ty + yy * 8];
    }
}

// ---------------- packed fp32x2 helpers -------------------------------------
__device__ __forceinline__ ull pk2(float lo, float hi) {
    ull r; asm("mov.b64 %0, {%1, %2};" : "=l"(r) : "f"(lo), "f"(hi)); return r;
}
__device__ __forceinline__ void upk(ull v, float& lo, float& hi) {
    asm("mov.b64 {%0, %1}, %2;" : "=f"(lo), "=f"(hi) : "l"(v));
}
__device__ __forceinline__ ull ffma2(ull a, ull b, ull c) {
    ull d; asm("fma.rn.f32x2 %0, %1, %2, %3;" : "=l"(d) : "l"(a), "l"(b), "l"(c)); return d;
}
__device__ __forceinline__ float fsig(float x) { return 1.0f / (1.0f + __expf(-x)); }

// ---------------- K-split dense: z partials into zb (slice0) / pb -----------
// WT is [DIN][ROWS]. slice s = tid/ACTIVE handles k in [s*KS,(s+1)*KS);
// lane r = tid%ACTIVE handles VEC consecutive rows. slice 0 adds bias ->
// zb[b*ROWS+row]; slice s>0 -> pb[(s-1)*ROWS*BPB + b*ROWS + row].
template<int ROWS, int DIN, int VEC, int S, int U>
__device__ __forceinline__ void dense_ks(
    const float* __restrict__ WT, const float* __restrict__ bias,
    const ull* __restrict__ xin, int xstride,          // dup-packed {v,v}
    float* __restrict__ zb, float* __restrict__ pb, int tid)
{
    constexpr int ACTIVE = ROWS / VEC;
    constexpr int KS = DIN / S;
    static_assert(ACTIVE * S <= NT2, "thread layout");
    static_assert((KS % U == 0 && KS > U) || KS < 32, "slice shape");
    if (tid >= ACTIVE * S) return;
    const int s  = tid / ACTIVE;
    const int r  = tid - s * ACTIVE;
    const int kb = s * KS;
    float* outp = (s == 0) ? zb : (pb + (s - 1) * (ROWS * BPB));
    const float* xf = reinterpret_cast<const float*>(xin);

    if constexpr (VEC == 4) {
        constexpr int W4 = ROWS / 4;
        const int r0 = r * 4;
        const ulonglong2* base = reinterpret_cast<const ulonglong2*>(WT) + r;
        ull acc[BPB][2];
#pragma unroll
        for (int b = 0; b < BPB; b++) {
            acc[b][0] = (s == 0) ? pk2(__ldg(bias + r0),     __ldg(bias + r0 + 1)) : 0ull;
            acc[b][1] = (s == 0) ? pk2(__ldg(bias + r0 + 2), __ldg(bias + r0 + 3)) : 0ull;
        }
        ulonglong2 buf[U];
#pragma unroll
        for (int u = 0; u < U; u++) buf[u] = __ldg(base + (kb + u) * W4);
        for (int k0 = 0; k0 < KS - U; k0 += U) {
#pragma unroll
            for (int u = 0; u < U; u++) {
                ull wlo = buf[u].x, whi = buf[u].y;
#pragma unroll
                for (int b = 0; b < BPB; b++) {
                    ull xd2 = xin[b * xstride + kb + k0 + u];
                    acc[b][0] = ffma2(wlo, xd2, acc[b][0]);
                    acc[b][1] = ffma2(whi, xd2, acc[b][1]);
                }
                buf[u] = __ldg(base + (kb + k0 + U + u) * W4);
            }
        }
#pragma unroll
        for (int u = 0; u < U; u++) {
            ull wlo = buf[u].x, whi = buf[u].y;
#pragma unroll
            for (int b = 0; b < BPB; b++) {
                ull xd2 = xin[b * xstride + kb + (KS - U) + u];
                acc[b][0] = ffma2(wlo, xd2, acc[b][0]);
                acc[b][1] = ffma2(whi, xd2, acc[b][1]);
            }
        }
#pragma unroll
        for (int b = 0; b < BPB; b++) {
            float l0, h0, l1, h1;
            upk(acc[b][0], l0, h0); upk(acc[b][1], l1, h1);
            outp[b * ROWS + r0]     = l0;
            outp[b * ROWS + r0 + 1] = h0;
            outp[b * ROWS + r0 + 2] = l1;
            outp[b * ROWS + r0 + 3] = h1;
        }
    } else if constexpr (VEC == 2) {
        constexpr int W2 = ROWS / 2;
        const int r0 = r * 2;
        const ull* base = reinterpret_cast<const ull*>(WT) + r;
        ull acc[BPB];
#pragma unroll
        for (int b = 0; b < BPB; b++)
            acc[b] = (s == 0) ? pk2(__ldg(bias + r0), __ldg(bias + r0 + 1)) : 0ull;
        ull buf[U];
#pragma unroll
        for (int u = 0; u < U; u++) buf[u] = __ldg(base + (kb + u) * W2);
        for (int k0 = 0; k0 < KS - U; k0 += U) {
#pragma unroll
            for (int u = 0; u < U; u++) {
                ull w = buf[u];
#pragma unroll
                for (int b = 0; b < BPB; b++)
                    acc[b] = ffma2(w, xin[b * xstride + kb + k0 + u], acc[b]);
                buf[u] = __ldg(base + (kb + k0 + U + u) * W2);
            }
        }
#pragma unroll
        for (int u = 0; u < U; u++) {
            ull w = buf[u];
#pragma unroll
            for (int b = 0; b < BPB; b++)
                acc[b] = ffma2(w, xin[b * xstride + kb + (KS - U) + u], acc[b]);
        }
#pragma unroll
        for (int b = 0; b < BPB; b++) {
            float lo, hi; upk(acc[b], lo, hi);
            outp[b * ROWS + r0]     = lo;
            outp[b * ROWS + r0 + 1] = hi;
        }
    } else {  // VEC == 1, scalar rows
        float acc[BPB];
        float bv = (s == 0) ? __ldg(bias + r) : 0.0f;
#pragma unroll
        for (int b = 0; b < BPB; b++) acc[b] = bv;
        if constexpr (KS >= 32) {
            float buf[U];
#pragma unroll
            for (int u = 0; u < U; u++) buf[u] = __ldg(WT + (kb + u) * ROWS + r);
            for (int k0 = 0; k0 < KS - U; k0 += U) {
#pragma unroll
                for (int u = 0; u < U; u++) {
                    float w = buf[u];
#pragma unroll
                    for (int b = 0; b < BPB; b++)
                        acc[b] = fmaf(w, xf[2 * (b * xstride + kb + k0 + u)], acc[b]);
                    buf[u] = __ldg(WT + (kb + k0 + U + u) * ROWS + r);
                }
            }
#pragma unroll
            for (int u = 0; u < U; u++) {
                float w = buf[u];
#pragma unroll
                for (int b = 0; b < BPB; b++)
                    acc[b] = fmaf(w, xf[2 * (b * xstride + kb + (KS - U) + u)], acc[b]);
            }
        } else {
#pragma unroll
            for (int k = 0; k < KS; k++) {
                float w = __ldg(WT + (kb + k) * ROWS + r);
#pragma unroll
                for (int b = 0; b < BPB; b++)
                    acc[b] = fmaf(w, xf[2 * (b * xstride + kb + k)], acc[b]);
            }
        }
#pragma unroll
        for (int b = 0; b < BPB; b++) outp[b * ROWS + r] = acc[b];
    }
}

// sum S partials, LSTM single-step combine (h0=c0=0) + outer tanh, dup-pack
template<int H, int S>
__device__ __forceinline__ void lstm_combine(
    const float* __restrict__ zb, const float* __restrict__ pb,
    ull* __restrict__ hd, int tid)
{
    constexpr int ROWS = 4 * H;
    for (int idx = tid; idx < H * BPB; idx += NT2) {
        int b = idx / H, j = idx - b * H;
        float zi = zb[b * ROWS + j];
        float zg = zb[b * ROWS + 2 * H + j];
        float zo = zb[b * ROWS + 3 * H + j];
#pragma unroll
        for (int s = 1; s < S; s++) {
            const float* p = pb + (s - 1) * (ROWS * BPB) + b * ROWS;
            zi += p[j]; zg += p[2 * H + j]; zo += p[3 * H + j];
        }
        float c = fsig(zi) * tanhf(zg);
        float h = tanhf(fsig(zo) * tanhf(c));
        hd[b * 256 + j] = pk2(h, h);
    }
}

// sum S partials + relu, dup-pack into hd (stride 256)
template<int ROWS, int S>
__device__ __forceinline__ void relu_combine(
    const float* __restrict__ zb, const float* __restrict__ pb,
    ull* __restrict__ hd, int tid)
{
    for (int idx = tid; idx < ROWS * BPB; idx += NT2) {
        int b = idx / ROWS, j = idx - b * ROWS;
        float v = zb[b * ROWS + j];
#pragma unroll
        for (int s = 1; s < S; s++)
            v += pb[(s - 1) * (ROWS * BPB) + b * ROWS + j];
        v = fmaxf(v, 0.0f);
        hd[b * 256 + j] = pk2(v, v);
    }
}

__global__ void __launch_bounds__(NT2, 1)
rnn_fwd_kernel(
    const float* __restrict__ x,
    const float* __restrict__ b1, const float* __restrict__ b2,
    const float* __restrict__ b3, const float* __restrict__ b4,
    const float* __restrict__ f1b, const float* __restrict__ f2b,
    const float* __restrict__ f3b,
    const float* __restrict__ f4w, const float* __restrict__ f4b,
    float* __restrict__ out)
{
    __shared__ float zb[BPB * 1024];   //  8 KB  slice-0 partials
    __shared__ float pb[BPB * 1024];   //  8 KB  slice 1..S-1 partials
    __shared__ ull   hA[BPB * 256];    //  4 KB  dup-packed activations
    __shared__ ull   hB[BPB * 256];    //  4 KB  (xd overlaid: dead ranges disjoint)

    ull* xd = hB;                      // x staging lives in hB until L1 dense done

    const int tid = threadIdx.x;
    const int b0  = blockIdx.x * BPB;

    // x is [T=1024, B=256, F=87]; need only t=0; dup-pack, zero-pad K to 96
    for (int i = tid; i < 96 * BPB; i += NT2) {
        int p = i / 96, f = i - p * 96;
        float v = (f < 87) ? __ldg(x + (b0 + p) * 87 + f) : 0.0f;
        xd[p * 96 + f] = pk2(v, v);
    }
    __syncthreads();

    // LSTM1: 87(->96) -> 256   rows=1024, VEC4, S=2, KS=48, U=8
    dense_ks<1024, 96, 4, 2, 8>(g_wt1, b1, xd, 96, zb, pb, tid);
    __syncthreads();
    lstm_combine<256, 2>(zb, pb, hA, tid);
    __syncthreads();

    // LSTM2: 256 -> 128        rows=512, VEC2, S=2, KS=128, U=16
    dense_ks<512, 256, 2, 2, 16>(g_wt2, b2, hA, 256, zb, pb, tid);
    __syncthreads();
    lstm_combine<128, 2>(zb, pb, hB, tid);
    __syncthreads();

    // LSTM3: 128 -> 64         rows=256, VEC1, S=2, KS=64, U=16
    dense_ks<256, 128, 1, 2, 16>(g_wt3, b3, hB, 256, zb, pb, tid);
    __syncthreads();
    lstm_combine<64, 2>(zb, pb, hA, tid);
    __syncthreads();

    // LSTM4: 64 -> 32          rows=128, VEC1, S=4, KS=16 (short path)
    dense_ks<128, 64, 1, 4, 8>(g_wt4, b4, hA, 256, zb, pb, tid);
    __syncthreads();
    lstm_combine<32, 4>(zb, pb, hB, tid);
    __syncthreads();

    // FC1: 32 -> 128 relu      rows=128, VEC1, S=4, KS=8 (short path)
    dense_ks<128, 32, 1, 4, 4>(g_ft1, f1b, hB, 256, zb, pb, tid);
    __syncthreads();
    relu_combine<128, 4>(zb, pb, hA, tid);
    __syncthreads();

    // FC2: 128 -> 64 relu      rows=64, VEC1, S=8, KS=16 (short path)
    dense_ks<64, 128, 1, 8, 8>(g_ft2, f2b, hA, 256, zb, pb, tid);
    __syncthreads();
    relu_combine<64, 8>(zb, pb, hB, tid);
    __syncthreads();

    // FC3: 64 -> 32 relu       rows=32, VEC1, S=8, KS=8 (short path)
    dense_ks<32, 64, 1, 8, 4>(g_ft3, f3b, hB, 256, zb, pb, tid);
    __syncthreads();
    relu_combine<32, 8>(zb, pb, hA, tid);
    __syncthreads();

    // FC4: 32 -> 3 (tiny, row-major direct)
    if (tid < 3 * BPB) {
        int b = tid / 3, r = tid - b * 3;
        float a = __ldg(f4b + r);
#pragma unroll
        for (int k = 0; k < 32; k++) {
            float lo, hi; upk(hA[b * 256 + k], lo, hi);
            a = fmaf(__ldg(f4w + r * 32 + k), lo, a);
        }
        out[(b0 + b) * 3 + r] = a;
    }
}

extern "C" void kernel_launch(void* const* d_in, const int* in_sizes, int n_in,
                              void* d_out, int out_size)
{
    const float* x   = (const float*)d_in[0];
    const float* w1i = (const float*)d_in[1];
    const float* b1  = (const float*)d_in[3];
    const float* w2i = (const float*)d_in[4];
    const float* b2  = (const float*)d_in[6];
    const float* w3i = (const float*)d_in[7];
    const float* b3  = (const float*)d_in[9];
    const float* w4i = (const float*)d_in[10];
    const float* b4  = (const float*)d_in[12];
    const float* f1w = (const float*)d_in[13];
    const float* f1b = (const float*)d_in[14];
    const float* f2w = (const float*)d_in[15];
    const float* f2b = (const float*)d_in[16];
    const float* f3w = (const float*)d_in[17];
    const float* f3b = (const float*)d_in[18];
    const float* f4w = (const float*)d_in[19];
    const float* f4b = (const float*)d_in[20];
    float* out = (float*)d_out;

    transpose_all_kernel<<<278, 256>>>(w1i, w2i, w3i, w4i, f1w, f2w, f3w);
    rnn_fwd_kernel<<<BATCH / BPB, NT2>>>(
        x, b1, b2, b3, b4, f1b, f2b, f3b, f4w, f4b, out);
}

// round 7
// speedup vs baseline: 2.9620x; 1.1451x over previous
#include <cuda_runtime.h>

typedef unsigned long long ull;

#define NT2  1024
#define BPB  2
#define BATCH 256

// ---------------- transposed-weight scratch (device globals: allowed) -------
__device__ __align__(16) float g_wt1[96  * 1024];
__device__ __align__(16) float g_wt2[256 * 512];
__device__ __align__(16) float g_wt3[128 * 256];
__device__ __align__(16) float g_wt4[64  * 128];
__device__ __align__(16) float g_ft1[32  * 128];
__device__ __align__(16) float g_ft2[128 * 64];
__device__ __align__(16) float g_ft3[64  * 32];

// ---------------- tiled transpose of all 7 matrices ------------------------
__global__ void __launch_bounds__(256)
transpose_all_kernel(const float* __restrict__ w1i, const float* __restrict__ w2i,
                     const float* __restrict__ w3i, const float* __restrict__ w4i,
                     const float* __restrict__ f1w, const float* __restrict__ f2w,
                     const float* __restrict__ f3w)
{
    __shared__ float tile[32][33];
    int bid = blockIdx.x;
    const float* src; float* dst; int R, C, Cpad, tcN, lb;

    if      (bid < 96)  { src = w1i; dst = g_wt1; R = 1024; C = 87;  Cpad = 96;  tcN = 3; lb = bid;       }
    else if (bid < 224) { src = w2i; dst = g_wt2; R = 512;  C = 256; Cpad = 256; tcN = 8; lb = bid - 96;  }
    else if (bid < 256) { src = w3i; dst = g_wt3; R = 256;  C = 128; Cpad = 128; tcN = 4; lb = bid - 224; }
    else if (bid < 264) { src = w4i; dst = g_wt4; R = 128;  C = 64;  Cpad = 64;  tcN = 2; lb = bid - 256; }
    else if (bid < 268) { src = f1w; dst = g_ft1; R = 128;  C = 32;  Cpad = 32;  tcN = 1; lb = bid - 264; }
    else if (bid < 276) { src = f2w; dst = g_ft2; R = 64;   C = 128; Cpad = 128; tcN = 4; lb = bid - 268; }
    else                { src = f3w; dst = g_ft3; R = 32;   C = 64;  Cpad = 64;  tcN = 2; lb = bid - 276; }

    const int tr = lb / tcN, tc = lb % tcN;
    const int tx = threadIdx.x & 31, ty = threadIdx.x >> 5;

#pragma unroll
    for (int yy = 0; yy < 4; yy++) {
        int r = tr * 32 + ty + yy * 8;
        int c = tc * 32 + tx;
        tile[ty + yy * 8][tx] = (r < R && c < C) ? src[r * C + c] : 0.0f;
    }
    __syncthreads();
#pragma unroll
    for (int yy = 0; yy < 4; yy++) {
        int c = tc * 32 + ty + yy * 8;
        int r = tr * 32 + tx;
        if (r < R && c < Cpad) dst[c * R + r] = tile[tx][ty + yy * 8];
    }
}

// ---------------- packed fp32x2 helpers -------------------------------------
__device__ __forceinline__ ull pk2(float lo, float hi) {
    ull r; asm("mov.b64 %0, {%1, %2};" : "=l"(r) : "f"(lo), "f"(hi)); return r;
}
__device__ __forceinline__ void upk(ull v, float& lo, float& hi) {
    asm("mov.b64 {%0, %1}, %2;" : "=f"(lo), "=f"(hi) : "l"(v));
}
__device__ __forceinline__ ull ffma2(ull a, ull b, ull c) {
    ull d; asm("fma.rn.f32x2 %0, %1, %2, %3;" : "=l"(d) : "l"(a), "l"(b), "l"(c)); return d;
}
__device__ __forceinline__ float fsig(float x) { return 1.0f / (1.0f + __expf(-x)); }

// ---------------- K-split dense: z partials into zb (slice0) / pb -----------
template<int ROWS, int DIN, int VEC, int S, int U>
__device__ __forceinline__ void dense_ks(
    const float* __restrict__ WT, const float* __restrict__ bias,
    const ull* __restrict__ xin, int xstride,          // dup-packed {v,v}
    float* __restrict__ zb, float* __restrict__ pb, int tid)
{
    constexpr int ACTIVE = ROWS / VEC;
    constexpr int KS = DIN / S;
    static_assert(ACTIVE * S <= NT2, "thread layout");
    static_assert((KS % U == 0 && KS > U) || KS < 32, "slice shape");
    if (tid >= ACTIVE * S) return;
    const int s  = tid / ACTIVE;
    const int r  = tid - s * ACTIVE;
    const int kb = s * KS;
    float* outp = (s == 0) ? zb : (pb + (s - 1) * (ROWS * BPB));
    const float* xf = reinterpret_cast<const float*>(xin);

    if constexpr (VEC == 4) {
        constexpr int W4 = ROWS / 4;
        const int r0 = r * 4;
        const ulonglong2* base = reinterpret_cast<const ulonglong2*>(WT) + r;
        ull acc[BPB][2];
#pragma unroll
        for (int b = 0; b < BPB; b++) {
            acc[b][0] = (s == 0) ? pk2(__ldg(bias + r0),     __ldg(bias + r0 + 1)) : 0ull;
            acc[b][1] = (s == 0) ? pk2(__ldg(bias + r0 + 2), __ldg(bias + r0 + 3)) : 0ull;
        }
        ulonglong2 buf[U];
#pragma unroll
        for (int u = 0; u < U; u++) buf[u] = __ldg(base + (kb + u) * W4);
        for (int k0 = 0; k0 < KS - U; k0 += U) {
#pragma unroll
            for (int u = 0; u < U; u++) {
                ull wlo = buf[u].x, whi = buf[u].y;
#pragma unroll
                for (int b = 0; b < BPB; b++) {
                    ull xd2 = xin[b * xstride + kb + k0 + u];
                    acc[b][0] = ffma2(wlo, xd2, acc[b][0]);
                    acc[b][1] = ffma2(whi, xd2, acc[b][1]);
                }
                buf[u] = __ldg(base + (kb + k0 + U + u) * W4);
            }
        }
#pragma unroll
        for (int u = 0; u < U; u++) {
            ull wlo = buf[u].x, whi = buf[u].y;
#pragma unroll
            for (int b = 0; b < BPB; b++) {
                ull xd2 = xin[b * xstride + kb + (KS - U) + u];
                acc[b][0] = ffma2(wlo, xd2, acc[b][0]);
                acc[b][1] = ffma2(whi, xd2, acc[b][1]);
            }
        }
#pragma unroll
        for (int b = 0; b < BPB; b++) {
            float l0, h0, l1, h1;
            upk(acc[b][0], l0, h0); upk(acc[b][1], l1, h1);
            outp[b * ROWS + r0]     = l0;
            outp[b * ROWS + r0 + 1] = h0;
            outp[b * ROWS + r0 + 2] = l1;
            outp[b * ROWS + r0 + 3] = h1;
        }
    } else if constexpr (VEC == 2) {
        constexpr int W2 = ROWS / 2;
        const int r0 = r * 2;
        const ull* base = reinterpret_cast<const ull*>(WT) + r;
        ull acc[BPB];
#pragma unroll
        for (int b = 0; b < BPB; b++)
            acc[b] = (s == 0) ? pk2(__ldg(bias + r0), __ldg(bias + r0 + 1)) : 0ull;
        if constexpr (KS > U && KS % U == 0) {
            ull buf[U];
#pragma unroll
            for (int u = 0; u < U; u++) buf[u] = __ldg(base + (kb + u) * W2);
            for (int k0 = 0; k0 < KS - U; k0 += U) {
#pragma unroll
                for (int u = 0; u < U; u++) {
                    ull w = buf[u];
#pragma unroll
                    for (int b = 0; b < BPB; b++)
                        acc[b] = ffma2(w, xin[b * xstride + kb + k0 + u], acc[b]);
                    buf[u] = __ldg(base + (kb + k0 + U + u) * W2);
                }
            }
#pragma unroll
            for (int u = 0; u < U; u++) {
                ull w = buf[u];
#pragma unroll
                for (int b = 0; b < BPB; b++)
                    acc[b] = ffma2(w, xin[b * xstride + kb + (KS - U) + u], acc[b]);
            }
        } else {
#pragma unroll
            for (int k = 0; k < KS; k++) {
                ull w = __ldg(base + (kb + k) * W2);
#pragma unroll
                for (int b = 0; b < BPB; b++)
                    acc[b] = ffma2(w, xin[b * xstride + kb + k], acc[b]);
            }
        }
#pragma unroll
        for (int b = 0; b < BPB; b++) {
            float lo, hi; upk(acc[b], lo, hi);
            outp[b * ROWS + r0]     = lo;
            outp[b * ROWS + r0 + 1] = hi;
        }
    } else {  // VEC == 1, scalar rows (short KS only)
        float acc[BPB];
        float bv = (s == 0) ? __ldg(bias + r) : 0.0f;
#pragma unroll
        for (int b = 0; b < BPB; b++) acc[b] = bv;
#pragma unroll
        for (int k = 0; k < KS; k++) {
            float w = __ldg(WT + (kb + k) * ROWS + r);
#pragma unroll
            for (int b = 0; b < BPB; b++)
                acc[b] = fmaf(w, xf[2 * (b * xstride + kb + k)], acc[b]);
        }
#pragma unroll
        for (int b = 0; b < BPB; b++) outp[b * ROWS + r] = acc[b];
    }
}

// sum S partials, LSTM single-step combine (h0=c0=0) + outer tanh, dup-pack
template<int H, int S>
__device__ __forceinline__ void lstm_combine(
    const float* __restrict__ zb, const float* __restrict__ pb,
    ull* __restrict__ hd, int tid)
{
    constexpr int ROWS = 4 * H;
    for (int idx = tid; idx < H * BPB; idx += NT2) {
        int b = idx / H, j = idx - b * H;
        float zi = zb[b * ROWS + j];
        float zg = zb[b * ROWS + 2 * H + j];
        float zo = zb[b * ROWS + 3 * H + j];
#pragma unroll
        for (int s = 1; s < S; s++) {
            const float* p = pb + (s - 1) * (ROWS * BPB) + b * ROWS;
            zi += p[j]; zg += p[2 * H + j]; zo += p[3 * H + j];
        }
        float c = fsig(zi) * tanhf(zg);
        float h = tanhf(fsig(zo) * tanhf(c));
        hd[b * 256 + j] = pk2(h, h);
    }
}

// sum S partials + relu, dup-pack into hd (stride 256)
template<int ROWS, int S>
__device__ __forceinline__ void relu_combine(
    const float* __restrict__ zb, const float* __restrict__ pb,
    ull* __restrict__ hd, int tid)
{
    for (int idx = tid; idx < ROWS * BPB; idx += NT2) {
        int b = idx / ROWS, j = idx - b * ROWS;
        float v = zb[b * ROWS + j];
#pragma unroll
        for (int s = 1; s < S; s++)
            v += pb[(s - 1) * (ROWS * BPB) + b * ROWS + j];
        v = fmaxf(v, 0.0f);
        hd[b * 256 + j] = pk2(v, v);
    }
}

__global__ void __launch_bounds__(NT2, 1)
rnn_fwd_kernel(
    const float* __restrict__ x,
    const float* __restrict__ b1, const float* __restrict__ b2,
    const float* __restrict__ b3, const float* __restrict__ b4,
    const float* __restrict__ f1b, const float* __restrict__ f2b,
    const float* __restrict__ f3b,
    const float* __restrict__ f4w, const float* __restrict__ f4b,
    float* __restrict__ out)
{
    __shared__ float zb[BPB * 1024];   //  8 KB  slice-0 partials
    __shared__ float pb[7 * 1024];     // 28 KB  slice 1..S-1 partials (max: L2 S=8)
    __shared__ ull   hA[BPB * 256];    //  4 KB  dup-packed activations
    __shared__ ull   hB[BPB * 256];    //  4 KB  (xd overlaid: dead ranges disjoint)

    ull* xd = hB;                      // x staging lives in hB until L1 dense done

    const int tid = threadIdx.x;
    const int b0  = blockIdx.x * BPB;

    // x is [T=1024, B=256, F=87]; need only t=0; dup-pack, zero-pad K to 96
    for (int i = tid; i < 96 * BPB; i += NT2) {
        int p = i / 96, f = i - p * 96;
        float v = (f < 87) ? __ldg(x + (b0 + p) * 87 + f) : 0.0f;
        xd[p * 96 + f] = pk2(v, v);
    }
    __syncthreads();

    // LSTM1: 87(->96) -> 256   rows=1024, VEC4, S=4, KS=24, U=8  (1024 thr)
    dense_ks<1024, 96, 4, 4, 8>(g_wt1, b1, xd, 96, zb, pb, tid);
    __syncthreads();
    lstm_combine<256, 4>(zb, pb, hA, tid);
    __syncthreads();

    // LSTM2: 256 -> 128        rows=512, VEC4, S=8, KS=32, U=8   (1024 thr)
    dense_ks<512, 256, 4, 8, 8>(g_wt2, b2, hA, 256, zb, pb, tid);
    __syncthreads();
    lstm_combine<128, 8>(zb, pb, hB, tid);
    __syncthreads();

    // LSTM3: 128 -> 64         rows=256, VEC2, S=8, KS=16, U=8   (1024 thr)
    dense_ks<256, 128, 2, 8, 8>(g_wt3, b3, hB, 256, zb, pb, tid);
    __syncthreads();
    lstm_combine<64, 8>(zb, pb, hA, tid);
    __syncthreads();

    // LSTM4: 64 -> 32          rows=128, VEC1, S=8, KS=8 (short) (1024 thr)
    dense_ks<128, 64, 1, 8, 4>(g_wt4, b4, hA, 256, zb, pb, tid);
    __syncthreads();
    lstm_combine<32, 8>(zb, pb, hB, tid);
    __syncthreads();

    // FC1: 32 -> 128 relu      rows=128, VEC1, S=8, KS=4 (short) (1024 thr)
    dense_ks<128, 32, 1, 8, 4>(g_ft1, f1b, hB, 256, zb, pb, tid);
    __syncthreads();
    relu_combine<128, 8>(zb, pb, hA, tid);
    __syncthreads();

    // FC2: 128 -> 64 relu      rows=64, VEC1, S=16, KS=8 (short) (1024 thr)
    dense_ks<64, 128, 1, 16, 4>(g_ft2, f2b, hA, 256, zb, pb, tid);
    __syncthreads();
    relu_combine<64, 16>(zb, pb, hB, tid);
    __syncthreads();

    // FC3: 64 -> 32 relu       rows=32, VEC1, S=16, KS=4 (short) (512 thr)
    dense_ks<32, 64, 1, 16, 4>(g_ft3, f3b, hB, 256, zb, pb, tid);
    __syncthreads();
    relu_combine<32, 16>(zb, pb, hA, tid);
    __syncthreads();

    // FC4: 32 -> 3, warp-parallel: warp w handles (b, r); lane = k
    if (tid < 3 * BPB * 32) {
        int w    = tid >> 5;          // 0..5
        int lane = tid & 31;
        int b    = w / 3, r = w - b * 3;
        float lo, hi; upk(hA[b * 256 + lane], lo, hi);
        float v = __ldg(f4w + r * 32 + lane) * lo;
#pragma unroll
        for (int off = 16; off > 0; off >>= 1)
            v += __shfl_xor_sync(0xFFFFFFFF, v, off);
        if (lane == 0) out[(b0 + b) * 3 + r] = v + __ldg(f4b + r);
    }
}

extern "C" void kernel_launch(void* const* d_in, const int* in_sizes, int n_in,
                              void* d_out, int out_size)
{
    const float* x   = (const float*)d_in[0];
    const float* w1i = (const float*)d_in[1];
    const float* b1  = (const float*)d_in[3];
    const float* w2i = (const float*)d_in[4];
    const float* b2  = (const float*)d_in[6];
    const float* w3i = (const float*)d_in[7];
    const float* b3  = (const float*)d_in[9];
    const float* w4i = (const float*)d_in[10];
    const float* b4  = (const float*)d_in[12];
    const float* f1w = (const float*)d_in[13];
    const float* f1b = (const float*)d_in[14];
    const float* f2w = (const float*)d_in[15];
    const float* f2b = (const float*)d_in[16];
    const float* f3w = (const float*)d_in[17];
    const float* f3b = (const float*)d_in[18];
    const float* f4w = (const float*)d_in[19];
    const float* f4b = (const float*)d_in[20];
    float* out = (float*)d_out;

    transpose_all_kernel<<<278, 256>>>(w1i, w2i, w3i, w4i, f1w, f2w, f3w);
    rnn_fwd_kernel<<<BATCH / BPB, NT2>>>(
        x, b1, b2, b3, b4, f1b, f2b, f3b, f4w, f4b, out);
}